// round 4
// baseline (speedup 1.0000x reference)
#include <cuda_runtime.h>
#include <cstdint>

#define N_NODES 100000
#define F_IN    256
#define H_DIM   16
#define C_DIM   40
#define E_MAX   3400000
#define SCAN_T  1024
#define SCAN_CHUNK 98   // 1024*98 >= 100000

// Device-global scratch (allocation-free per harness rules)
__device__ __align__(128) float g_H1[N_NODES * H_DIM];     // x @ W1
__device__ __align__(128) float g_R[N_NODES * H_DIM];      // relu(agg1 + b1)
__device__ __align__(128) float g_AGG16[N_NODES * H_DIM];  // 16-dim agg, layer 2
__device__ __align__(16)  int2  g_EDGE[E_MAX];             // packed (src, dst)
__device__ __align__(16)  int2  g_SREC[E_MAX];             // (src, w_bits) sorted by dst
__device__ int g_DEG[N_NODES];
__device__ int g_ROWPTR[N_NODES];
__device__ int g_CUR[N_NODES];
__device__ int g_is64;

// ---------------------------------------------------------------------------
// k_detect: int64 vs int32 edge_index (odd 32-bit words all zero <=> int64).
// ---------------------------------------------------------------------------
__global__ void k_detect(const unsigned int* __restrict__ ei32) {
    int lane = threadIdx.x;
    bool ok = true;
    #pragma unroll
    for (int i = 0; i < 16; i++) {
        int pos = 2 * (lane * 16 + i) + 1;
        ok &= (ei32[pos] == 0u);
    }
    bool all64 = __all_sync(0xFFFFFFFFu, ok);
    if (lane == 0) g_is64 = all64 ? 1 : 0;
}

// ---------------------------------------------------------------------------
__global__ void k_zero_deg() {
    int i = blockIdx.x * blockDim.x + threadIdx.x;
    if (i < N_NODES) g_DEG[i] = 0;
}

// ---------------------------------------------------------------------------
// k_convert_hist: pack (src,dst) int2 + histogram of dst.
// ---------------------------------------------------------------------------
__global__ void k_convert_hist(const void* __restrict__ ei, int E) {
    int e = blockIdx.x * blockDim.x + threadIdx.x;
    if (e >= E) return;
    int s, d;
    if (g_is64) {
        const long long* p = (const long long*)ei;
        s = (int)p[e]; d = (int)p[E + e];
    } else {
        const int* p = (const int*)ei;
        s = p[e]; d = p[E + e];
    }
    g_EDGE[e] = make_int2(s, d);
    atomicAdd(&g_DEG[d], 1);
}

// ---------------------------------------------------------------------------
// k_scan: single-block exclusive prefix sum of g_DEG -> g_ROWPTR, g_CUR.
// ---------------------------------------------------------------------------
__global__ void k_scan() {
    __shared__ int ssum[SCAN_T];
    int t = threadIdx.x;
    int start = t * SCAN_CHUNK;
    int s = 0;
    for (int i = 0; i < SCAN_CHUNK; i++) {
        int idx = start + i;
        if (idx < N_NODES) s += g_DEG[idx];
    }
    ssum[t] = s;
    __syncthreads();
    for (int off = 1; off < SCAN_T; off <<= 1) {
        int v = (t >= off) ? ssum[t - off] : 0;
        __syncthreads();
        ssum[t] += v;
        __syncthreads();
    }
    int run = (t == 0) ? 0 : ssum[t - 1];
    for (int i = 0; i < SCAN_CHUNK; i++) {
        int idx = start + i;
        if (idx < N_NODES) {
            g_ROWPTR[idx] = run;
            g_CUR[idx]    = run;
            run += g_DEG[idx];
        }
    }
}

// ---------------------------------------------------------------------------
// k_fill: scatter (src, w) records into dst-sorted order via atomic cursors.
// ---------------------------------------------------------------------------
__global__ void k_fill(const float* __restrict__ ew, int E) {
    int e = blockIdx.x * blockDim.x + threadIdx.x;
    if (e >= E) return;
    int2 sd = g_EDGE[e];
    float w = __ldg(ew + e);
    int pos = atomicAdd(&g_CUR[sd.y], 1);
    g_SREC[pos] = make_int2(sd.x, __float_as_int(w));
}

// ---------------------------------------------------------------------------
// k_gemm1: g_H1 = x @ W1 (thread-per-node, W1 in smem).
// ---------------------------------------------------------------------------
__global__ void k_gemm1(const float* __restrict__ x, const float* __restrict__ W1) {
    __shared__ float4 Ws[F_IN][4];
    const float4* W4 = (const float4*)W1;
    for (int i = threadIdx.x; i < F_IN * 4; i += blockDim.x)
        Ws[i >> 2][i & 3] = W4[i];
    __syncthreads();

    int n = blockIdx.x * blockDim.x + threadIdx.x;
    if (n >= N_NODES) return;

    float acc[16];
    #pragma unroll
    for (int j = 0; j < 16; j++) acc[j] = 0.f;

    const float4* xr = (const float4*)(x + (size_t)n * F_IN);
    #pragma unroll 4
    for (int kk = 0; kk < F_IN / 4; kk++) {
        float4 xv = xr[kk];
        float xs[4] = {xv.x, xv.y, xv.z, xv.w};
        #pragma unroll
        for (int r = 0; r < 4; r++) {
            int k = kk * 4 + r;
            float4 w0 = Ws[k][0], w1 = Ws[k][1], w2 = Ws[k][2], w3 = Ws[k][3];
            float v = xs[r];
            acc[0]  += v * w0.x; acc[1]  += v * w0.y; acc[2]  += v * w0.z; acc[3]  += v * w0.w;
            acc[4]  += v * w1.x; acc[5]  += v * w1.y; acc[6]  += v * w1.z; acc[7]  += v * w1.w;
            acc[8]  += v * w2.x; acc[9]  += v * w2.y; acc[10] += v * w2.z; acc[11] += v * w2.w;
            acc[12] += v * w3.x; acc[13] += v * w3.y; acc[14] += v * w3.z; acc[15] += v * w3.w;
        }
    }

    float4* h = (float4*)(g_H1 + (size_t)n * H_DIM);
    h[0] = make_float4(acc[0],  acc[1],  acc[2],  acc[3]);
    h[1] = make_float4(acc[4],  acc[5],  acc[6],  acc[7]);
    h[2] = make_float4(acc[8],  acc[9],  acc[10], acc[11]);
    h[3] = make_float4(acc[12], acc[13], acc[14], acc[15]);
}

// ---------------------------------------------------------------------------
// k_agg<PHASE>: warp-per-node gather aggregation (no atomics).
//   8 groups x 4 lanes; group g handles edge (base+g), its 4 lanes hold quad q.
//   PHASE 0: g_H1 -> relu(. + b1) -> g_R      PHASE 1: g_R -> g_AGG16
// ---------------------------------------------------------------------------
template <int PHASE>
__global__ void k_agg(const float* __restrict__ b1) {
    int warp_id = (blockIdx.x * blockDim.x + threadIdx.x) >> 5;
    if (warp_id >= N_NODES) return;
    int lane = threadIdx.x & 31;
    int g = lane >> 2;
    int q = lane & 3;

    const float* feat = (PHASE == 0) ? g_H1 : g_R;
    int start = g_ROWPTR[warp_id];
    int deg   = g_DEG[warp_id];

    float4 acc = make_float4(0.f, 0.f, 0.f, 0.f);
    for (int base = 0; base < deg; base += 8) {
        int i = base + g;
        if (i < deg) {
            int2 rec = g_SREC[start + i];
            float w = __int_as_float(rec.y);
            float4 v = ((const float4*)(feat + (size_t)rec.x * H_DIM))[q];
            acc.x += w * v.x; acc.y += w * v.y; acc.z += w * v.z; acc.w += w * v.w;
        }
    }
    // Reduce across the 8 groups (lanes with identical q): offsets 4, 8, 16.
    #pragma unroll
    for (int off = 4; off <= 16; off <<= 1) {
        acc.x += __shfl_xor_sync(0xFFFFFFFFu, acc.x, off);
        acc.y += __shfl_xor_sync(0xFFFFFFFFu, acc.y, off);
        acc.z += __shfl_xor_sync(0xFFFFFFFFu, acc.z, off);
        acc.w += __shfl_xor_sync(0xFFFFFFFFu, acc.w, off);
    }
    if (lane < 4) {
        if (PHASE == 0) {
            float4 b = ((const float4*)b1)[lane];
            acc.x = fmaxf(acc.x + b.x, 0.f);
            acc.y = fmaxf(acc.y + b.y, 0.f);
            acc.z = fmaxf(acc.z + b.z, 0.f);
            acc.w = fmaxf(acc.w + b.w, 0.f);
            ((float4*)(g_R + (size_t)warp_id * H_DIM))[lane] = acc;
        } else {
            ((float4*)(g_AGG16 + (size_t)warp_id * H_DIM))[lane] = acc;
        }
    }
}

// ---------------------------------------------------------------------------
// k_out: out = log_softmax(g_AGG16 @ W2 + b2, axis=1)
// ---------------------------------------------------------------------------
__global__ void k_out(const float* __restrict__ W2, const float* __restrict__ b2,
                      float* __restrict__ out) {
    __shared__ float4 W2s[16][10];
    __shared__ float  b2s[C_DIM];
    for (int i = threadIdx.x; i < 160; i += blockDim.x)
        W2s[i / 10][i % 10] = ((const float4*)W2)[i];
    if (threadIdx.x < C_DIM) b2s[threadIdx.x] = b2[threadIdx.x];
    __syncthreads();

    int n = blockIdx.x * blockDim.x + threadIdx.x;
    if (n >= N_NODES) return;

    float v[16];
    const float4* ar = (const float4*)(g_AGG16 + (size_t)n * H_DIM);
    #pragma unroll
    for (int i = 0; i < 4; i++) {
        float4 t = ar[i];
        v[4*i] = t.x; v[4*i+1] = t.y; v[4*i+2] = t.z; v[4*i+3] = t.w;
    }

    float o[C_DIM];
    #pragma unroll
    for (int j = 0; j < C_DIM; j++) o[j] = b2s[j];
    #pragma unroll
    for (int i = 0; i < 16; i++) {
        float vi = v[i];
        #pragma unroll
        for (int j = 0; j < 10; j++) {
            float4 w = W2s[i][j];
            o[4*j+0] += vi * w.x; o[4*j+1] += vi * w.y;
            o[4*j+2] += vi * w.z; o[4*j+3] += vi * w.w;
        }
    }

    float m = o[0];
    #pragma unroll
    for (int j = 1; j < C_DIM; j++) m = fmaxf(m, o[j]);
    float s = 0.f;
    #pragma unroll
    for (int j = 0; j < C_DIM; j++) s += __expf(o[j] - m);
    float ls = __logf(s) + m;

    float4* op = (float4*)(out + (size_t)n * C_DIM);
    #pragma unroll
    for (int j = 0; j < 10; j++)
        op[j] = make_float4(o[4*j] - ls, o[4*j+1] - ls, o[4*j+2] - ls, o[4*j+3] - ls);
}

// ---------------------------------------------------------------------------
extern "C" void kernel_launch(void* const* d_in, const int* in_sizes, int n_in,
                              void* d_out, int out_size) {
    const float* x  = (const float*)d_in[0];
    const void*  ei = d_in[1];
    const float* ew = (const float*)d_in[2];
    const float* W1 = (const float*)d_in[3];
    const float* b1 = (const float*)d_in[4];
    const float* W2 = (const float*)d_in[5];
    const float* b2 = (const float*)d_in[6];
    int E = in_sizes[2];

    int nb_nodes = (N_NODES + 255) / 256;
    int nb_edges = (E + 255) / 256;
    int nb_warp_nodes = (N_NODES * 32 + 255) / 256;   // warp per node

    k_detect      <<<1, 32>>>((const unsigned int*)ei);
    k_zero_deg    <<<nb_nodes, 256>>>();
    k_convert_hist<<<nb_edges, 256>>>(ei, E);
    k_scan        <<<1, SCAN_T>>>();
    k_fill        <<<nb_edges, 256>>>(ew, E);
    k_gemm1       <<<nb_nodes, 256>>>(x, W1);
    k_agg<0>      <<<nb_warp_nodes, 256>>>(b1);
    k_agg<1>      <<<nb_warp_nodes, 256>>>(b1);
    k_out         <<<nb_nodes, 256>>>(W2, b2, (float*)d_out);
}

// round 5
// speedup vs baseline: 1.7256x; 1.7256x over previous
#include <cuda_runtime.h>
#include <cstdint>

#define N_NODES 100000
#define F_IN    256
#define H_DIM   16
#define C_DIM   40
#define E_MAX   3400000
#define NB_SCAN ((N_NODES + 255) / 256)

// Device-global scratch (allocation-free per harness rules)
__device__ __align__(128) float g_H1[N_NODES * H_DIM];     // x @ W1
__device__ __align__(128) float g_R[N_NODES * H_DIM];      // relu(agg1 + b1)
__device__ __align__(128) float g_AGG16[N_NODES * H_DIM];  // 16-dim agg, layer 2
__device__ __align__(16)  int2  g_EDGE[E_MAX];             // packed (src, dst)
__device__ __align__(16)  int2  g_SREC[E_MAX];             // (src, w_bits) sorted by dst
__device__ int g_DEG[N_NODES];
__device__ int g_ROWPTR[N_NODES];
__device__ int g_CUR[N_NODES];
__device__ int g_BLKSUM[NB_SCAN + 1];
__device__ int g_is64;

// ---------------------------------------------------------------------------
// k_detect: int64 vs int32 edge_index (odd 32-bit words all zero <=> int64).
// ---------------------------------------------------------------------------
__global__ void k_detect(const unsigned int* __restrict__ ei32) {
    int lane = threadIdx.x;
    bool ok = true;
    #pragma unroll
    for (int i = 0; i < 16; i++) {
        int pos = 2 * (lane * 16 + i) + 1;
        ok &= (ei32[pos] == 0u);
    }
    bool all64 = __all_sync(0xFFFFFFFFu, ok);
    if (lane == 0) g_is64 = all64 ? 1 : 0;
}

// ---------------------------------------------------------------------------
__global__ void k_zero_deg() {
    int i = blockIdx.x * blockDim.x + threadIdx.x;
    if (i < N_NODES) g_DEG[i] = 0;
}

// ---------------------------------------------------------------------------
// k_convert_hist: pack (src,dst) int2 + histogram of dst.
// ---------------------------------------------------------------------------
__global__ void k_convert_hist(const void* __restrict__ ei, int E) {
    int e = blockIdx.x * blockDim.x + threadIdx.x;
    if (e >= E) return;
    int s, d;
    if (g_is64) {
        const long long* p = (const long long*)ei;
        s = (int)p[e]; d = (int)p[E + e];
    } else {
        const int* p = (const int*)ei;
        s = p[e]; d = p[E + e];
    }
    g_EDGE[e] = make_int2(s, d);
    atomicAdd(&g_DEG[d], 1);
}

// ---------------------------------------------------------------------------
// Hierarchical scan (3 kernels): block-local scan -> scan block sums -> add.
// ---------------------------------------------------------------------------
__global__ void k_scan1() {
    int i = blockIdx.x * 256 + threadIdx.x;
    int v = (i < N_NODES) ? g_DEG[i] : 0;
    int lane = threadIdx.x & 31, wid = threadIdx.x >> 5;

    int s = v;  // inclusive warp scan
    #pragma unroll
    for (int off = 1; off < 32; off <<= 1) {
        int t = __shfl_up_sync(0xFFFFFFFFu, s, off);
        if (lane >= off) s += t;
    }
    __shared__ int wsum[8];
    if (lane == 31) wsum[wid] = s;
    __syncthreads();
    if (wid == 0) {
        int ws = (lane < 8) ? wsum[lane] : 0;
        #pragma unroll
        for (int off = 1; off < 8; off <<= 1) {
            int t = __shfl_up_sync(0xFFFFFFFFu, ws, off);
            if (lane >= off) ws += t;
        }
        if (lane < 8) wsum[lane] = ws;
    }
    __syncthreads();
    int excl = s - v + (wid > 0 ? wsum[wid - 1] : 0);
    if (i < N_NODES) g_ROWPTR[i] = excl;           // block-local exclusive
    if (threadIdx.x == 255) g_BLKSUM[blockIdx.x] = excl + v;  // block total
}

__global__ void k_scan2(int nblk) {   // single block, 512 threads (16 warps)
    int t = threadIdx.x;
    int v = (t < nblk) ? g_BLKSUM[t] : 0;
    int lane = t & 31, wid = t >> 5;

    int s = v;
    #pragma unroll
    for (int off = 1; off < 32; off <<= 1) {
        int u = __shfl_up_sync(0xFFFFFFFFu, s, off);
        if (lane >= off) s += u;
    }
    __shared__ int wsum[16];
    if (lane == 31) wsum[wid] = s;
    __syncthreads();
    if (wid == 0) {
        int ws = (lane < 16) ? wsum[lane] : 0;
        #pragma unroll
        for (int off = 1; off < 16; off <<= 1) {
            int u = __shfl_up_sync(0xFFFFFFFFu, ws, off);
            if (lane >= off) ws += u;
        }
        if (lane < 16) wsum[lane] = ws;
    }
    __syncthreads();
    int excl = s - v + (wid > 0 ? wsum[wid - 1] : 0);
    if (t < nblk) g_BLKSUM[t] = excl;
}

__global__ void k_scan3() {
    int i = blockIdx.x * 256 + threadIdx.x;
    if (i >= N_NODES) return;
    int r = g_ROWPTR[i] + g_BLKSUM[blockIdx.x];
    g_ROWPTR[i] = r;
    g_CUR[i]    = r;
}

// ---------------------------------------------------------------------------
// k_fill: scatter (src, w) records into dst-sorted order via atomic cursors.
// ---------------------------------------------------------------------------
__global__ void k_fill(const float* __restrict__ ew, int E) {
    int e = blockIdx.x * blockDim.x + threadIdx.x;
    if (e >= E) return;
    int2 sd = g_EDGE[e];
    float w = __ldg(ew + e);
    int pos = atomicAdd(&g_CUR[sd.y], 1);
    g_SREC[pos] = make_int2(sd.x, __float_as_int(w));
}

// ---------------------------------------------------------------------------
// k_gemm1: g_H1 = x @ W1 (thread-per-node, W1 in smem).
// ---------------------------------------------------------------------------
__global__ void k_gemm1(const float* __restrict__ x, const float* __restrict__ W1) {
    __shared__ float4 Ws[F_IN][4];
    const float4* W4 = (const float4*)W1;
    for (int i = threadIdx.x; i < F_IN * 4; i += blockDim.x)
        Ws[i >> 2][i & 3] = W4[i];
    __syncthreads();

    int n = blockIdx.x * blockDim.x + threadIdx.x;
    if (n >= N_NODES) return;

    float acc[16];
    #pragma unroll
    for (int j = 0; j < 16; j++) acc[j] = 0.f;

    const float4* xr = (const float4*)(x + (size_t)n * F_IN);
    #pragma unroll 4
    for (int kk = 0; kk < F_IN / 4; kk++) {
        float4 xv = xr[kk];
        float xs[4] = {xv.x, xv.y, xv.z, xv.w};
        #pragma unroll
        for (int r = 0; r < 4; r++) {
            int k = kk * 4 + r;
            float4 w0 = Ws[k][0], w1 = Ws[k][1], w2 = Ws[k][2], w3 = Ws[k][3];
            float v = xs[r];
            acc[0]  += v * w0.x; acc[1]  += v * w0.y; acc[2]  += v * w0.z; acc[3]  += v * w0.w;
            acc[4]  += v * w1.x; acc[5]  += v * w1.y; acc[6]  += v * w1.z; acc[7]  += v * w1.w;
            acc[8]  += v * w2.x; acc[9]  += v * w2.y; acc[10] += v * w2.z; acc[11] += v * w2.w;
            acc[12] += v * w3.x; acc[13] += v * w3.y; acc[14] += v * w3.z; acc[15] += v * w3.w;
        }
    }

    float4* h = (float4*)(g_H1 + (size_t)n * H_DIM);
    h[0] = make_float4(acc[0],  acc[1],  acc[2],  acc[3]);
    h[1] = make_float4(acc[4],  acc[5],  acc[6],  acc[7]);
    h[2] = make_float4(acc[8],  acc[9],  acc[10], acc[11]);
    h[3] = make_float4(acc[12], acc[13], acc[14], acc[15]);
}

// ---------------------------------------------------------------------------
// k_agg<PHASE>: warp-per-node gather aggregation (no atomics).
//   8 groups x 4 lanes; group g handles edge (base+g), its 4 lanes hold quad q.
//   PHASE 0: g_H1 -> relu(. + b1) -> g_R      PHASE 1: g_R -> g_AGG16
// ---------------------------------------------------------------------------
template <int PHASE>
__global__ void k_agg(const float* __restrict__ b1) {
    int warp_id = (blockIdx.x * blockDim.x + threadIdx.x) >> 5;
    if (warp_id >= N_NODES) return;
    int lane = threadIdx.x & 31;
    int g = lane >> 2;
    int q = lane & 3;

    const float* feat = (PHASE == 0) ? g_H1 : g_R;
    int start = g_ROWPTR[warp_id];
    int deg   = g_DEG[warp_id];

    float4 acc = make_float4(0.f, 0.f, 0.f, 0.f);
    for (int base = 0; base < deg; base += 8) {
        int i = base + g;
        if (i < deg) {
            int2 rec = g_SREC[start + i];
            float w = __int_as_float(rec.y);
            float4 v = ((const float4*)(feat + (size_t)rec.x * H_DIM))[q];
            acc.x += w * v.x; acc.y += w * v.y; acc.z += w * v.z; acc.w += w * v.w;
        }
    }
    #pragma unroll
    for (int off = 4; off <= 16; off <<= 1) {
        acc.x += __shfl_xor_sync(0xFFFFFFFFu, acc.x, off);
        acc.y += __shfl_xor_sync(0xFFFFFFFFu, acc.y, off);
        acc.z += __shfl_xor_sync(0xFFFFFFFFu, acc.z, off);
        acc.w += __shfl_xor_sync(0xFFFFFFFFu, acc.w, off);
    }
    if (lane < 4) {
        if (PHASE == 0) {
            float4 b = ((const float4*)b1)[lane];
            acc.x = fmaxf(acc.x + b.x, 0.f);
            acc.y = fmaxf(acc.y + b.y, 0.f);
            acc.z = fmaxf(acc.z + b.z, 0.f);
            acc.w = fmaxf(acc.w + b.w, 0.f);
            ((float4*)(g_R + (size_t)warp_id * H_DIM))[lane] = acc;
        } else {
            ((float4*)(g_AGG16 + (size_t)warp_id * H_DIM))[lane] = acc;
        }
    }
}

// ---------------------------------------------------------------------------
// k_out: out = log_softmax(g_AGG16 @ W2 + b2, axis=1)
// ---------------------------------------------------------------------------
__global__ void k_out(const float* __restrict__ W2, const float* __restrict__ b2,
                      float* __restrict__ out) {
    __shared__ float4 W2s[16][10];
    __shared__ float  b2s[C_DIM];
    for (int i = threadIdx.x; i < 160; i += blockDim.x)
        W2s[i / 10][i % 10] = ((const float4*)W2)[i];
    if (threadIdx.x < C_DIM) b2s[threadIdx.x] = b2[threadIdx.x];
    __syncthreads();

    int n = blockIdx.x * blockDim.x + threadIdx.x;
    if (n >= N_NODES) return;

    float v[16];
    const float4* ar = (const float4*)(g_AGG16 + (size_t)n * H_DIM);
    #pragma unroll
    for (int i = 0; i < 4; i++) {
        float4 t = ar[i];
        v[4*i] = t.x; v[4*i+1] = t.y; v[4*i+2] = t.z; v[4*i+3] = t.w;
    }

    float o[C_DIM];
    #pragma unroll
    for (int j = 0; j < C_DIM; j++) o[j] = b2s[j];
    #pragma unroll
    for (int i = 0; i < 16; i++) {
        float vi = v[i];
        #pragma unroll
        for (int j = 0; j < 10; j++) {
            float4 w = W2s[i][j];
            o[4*j+0] += vi * w.x; o[4*j+1] += vi * w.y;
            o[4*j+2] += vi * w.z; o[4*j+3] += vi * w.w;
        }
    }

    float m = o[0];
    #pragma unroll
    for (int j = 1; j < C_DIM; j++) m = fmaxf(m, o[j]);
    float s = 0.f;
    #pragma unroll
    for (int j = 0; j < C_DIM; j++) s += __expf(o[j] - m);
    float ls = __logf(s) + m;

    float4* op = (float4*)(out + (size_t)n * C_DIM);
    #pragma unroll
    for (int j = 0; j < 10; j++)
        op[j] = make_float4(o[4*j] - ls, o[4*j+1] - ls, o[4*j+2] - ls, o[4*j+3] - ls);
}

// ---------------------------------------------------------------------------
extern "C" void kernel_launch(void* const* d_in, const int* in_sizes, int n_in,
                              void* d_out, int out_size) {
    const float* x  = (const float*)d_in[0];
    const void*  ei = d_in[1];
    const float* ew = (const float*)d_in[2];
    const float* W1 = (const float*)d_in[3];
    const float* b1 = (const float*)d_in[4];
    const float* W2 = (const float*)d_in[5];
    const float* b2 = (const float*)d_in[6];
    int E = in_sizes[2];

    int nb_nodes = NB_SCAN;
    int nb_edges = (E + 255) / 256;
    int nb_warp_nodes = (N_NODES * 32 + 255) / 256;   // warp per node

    k_detect      <<<1, 32>>>((const unsigned int*)ei);
    k_zero_deg    <<<nb_nodes, 256>>>();
    k_convert_hist<<<nb_edges, 256>>>(ei, E);
    k_scan1       <<<nb_nodes, 256>>>();
    k_scan2       <<<1, 512>>>(nb_nodes);
    k_scan3       <<<nb_nodes, 256>>>();
    k_fill        <<<nb_edges, 256>>>(ew, E);
    k_gemm1       <<<nb_nodes, 256>>>(x, W1);
    k_agg<0>      <<<nb_warp_nodes, 256>>>(b1);
    k_agg<1>      <<<nb_warp_nodes, 256>>>(b1);
    k_out         <<<nb_nodes, 256>>>(W2, b2, (float*)d_out);
}